// round 12
// baseline (speedup 1.0000x reference)
#include <cuda_runtime.h>
#include <cuda_bf16.h>
#include <cstdint>

// Problem shapes (fixed by setup_inputs): B=4, N=128, C_IN=C_OUT=32, X=3.
#define BZ 4
#define NN 128

// ---------------------------------------------------------------------------
// Scratch (no allocations allowed -> __device__ globals)
// ---------------------------------------------------------------------------
// Per-(z,c) BASE sums: row = 128 floats [b][k]: b=0: p0 = sum_d f;
// b=1..3: p1[x] = sum_d g[d,x]*f.
__device__ float4 g_base[BZ][NN][32];     // 256 KB
__device__ float  g_W12g[9 * 32 * 32];    // W12[yx][i][k] = sum_j W2[y,i,j]*W1[x,j,k]
// Per-(z,a) expansion coefficients, pre-scaled by 1/n:
//   slot 0..31: V0[i]; slot 32+x*32+i: V1[x][i]
__device__ float  g_V[BZ][NN][128];       // 256 KB

// Robust scalar load: handles int32 or float32 encodings of n_norm.
__device__ __forceinline__ float load_scalar_f(const void* p) {
    int iv = *(const int*)p;
    int ex = (iv >> 23) & 0xFF;
    if (ex > 60 && ex < 200) return __int_as_float(iv);
    return (float)iv;
}

// ---------------------------------------------------------------------------
// K1: grid = BZ*NN + 9, 256 threads, regs capped (r10 lesson: rider path must
// not inflate the main path's allocation).
//   blocks [0..511]: per-(z,c) base sums (proven r7/r11 loop shape).
//   blocks [512..520]: W12[yx] = W2[y] @ W1[x] via smem staging (reg-light).
// ---------------------------------------------------------------------------
__global__ void __launch_bounds__(256, 6) k_partial(const float* __restrict__ feat,
                                                    const float* __restrict__ geo,
                                                    const float* __restrict__ W1,
                                                    const float* __restrict__ W2) {
    int zc = blockIdx.x;
    int t = threadIdx.x;        // 256

    // ---- W12 rider blocks: stage weights in smem, then LDS-fed FMA chains ----
    if (zc >= BZ * NN) {
        __shared__ float sw1[1024];   // W1[x][j][k]
        __shared__ float sw2[1024];   // W2[y][i][j]
        int yx = zc - BZ * NN;        // 0..8
        int y = yx / 3, x = yx - y * 3;
        #pragma unroll
        for (int r = 0; r < 4; r++) {
            sw2[t + r * 256] = W2[y * 1024 + t + r * 256];
            sw1[t + r * 256] = W1[x * 1024 + t + r * 256];
        }
        __syncthreads();
        #pragma unroll
        for (int r = 0; r < 4; r++) {
            int idx = t + r * 256;    // i*32 + k
            int i = idx >> 5, k = idx & 31;
            float acc = 0.f;
            #pragma unroll
            for (int j = 0; j < 32; j++) acc = fmaf(sw2[i * 32 + j], sw1[j * 32 + k], acc);
            g_W12g[yx * 1024 + idx] = acc;
        }
        return;
    }

    int z = zc >> 7;
    int kq   = t & 7;           // which float4 within the 32-float k-row
    int dgrp = t >> 3;          // 0..31

    __shared__ float  sgeo[3][NN];     // geo[z] transposed: [comp][d]
    __shared__ float4 smq[4][32][8];   // [comp][dgrp][kq], 16 KB
    __shared__ float  red[4][32];      // reduced sums [comp][k]

    if (t < NN * 3) {
        int d = t / 3, comp = t - d * 3;
        sgeo[comp][d] = geo[z * NN * 3 + t];
    }
    if (t + 256 < NN * 3) {
        int idx = t + 256;
        int d = idx / 3, comp = idx - d * 3;
        sgeo[comp][d] = geo[z * NN * 3 + idx];
    }
    __syncthreads();

    const float4* f4 = (const float4*)(feat + ((size_t)zc << 12));
    float4 s0 = make_float4(0.f, 0.f, 0.f, 0.f);
    float4 sx = s0, sy = s0, sz2 = s0;

    #pragma unroll
    for (int it = 0; it < 4; it++) {
        int d = dgrp + it * 32;
        float4 f = f4[d * 8 + kq];
        float g0 = sgeo[0][d], g1 = sgeo[1][d], g2 = sgeo[2][d];
        s0.x += f.x;  s0.y += f.y;  s0.z += f.z;  s0.w += f.w;
        sx.x = fmaf(f.x, g0, sx.x);  sx.y = fmaf(f.y, g0, sx.y);
        sx.z = fmaf(f.z, g0, sx.z);  sx.w = fmaf(f.w, g0, sx.w);
        sy.x = fmaf(f.x, g1, sy.x);  sy.y = fmaf(f.y, g1, sy.y);
        sy.z = fmaf(f.z, g1, sy.z);  sy.w = fmaf(f.w, g1, sy.w);
        sz2.x = fmaf(f.x, g2, sz2.x);  sz2.y = fmaf(f.y, g2, sz2.y);
        sz2.z = fmaf(f.z, g2, sz2.z);  sz2.w = fmaf(f.w, g2, sz2.w);
    }

    smq[0][dgrp][kq] = s0;
    smq[1][dgrp][kq] = sx;
    smq[2][dgrp][kq] = sy;
    smq[3][dgrp][kq] = sz2;
    __syncthreads();

    // Reduce over 32 dgrps: threads t<128 -> (comp = t>>5, k = t&31).
    if (t < 128) {
        int comp = t >> 5;
        int k = t & 31;
        const float* p = (const float*)&smq[comp][0][0];  // 1024 floats
        float s = 0.f;
        #pragma unroll
        for (int dg = 0; dg < 32; dg++) s += p[dg * 32 + k];
        red[comp][k] = s;
    }
    __syncthreads();

    // Write the 128-float base row as 32 float4s (coalesced 512B).
    if (t < 32) {
        int c = zc & (NN - 1);
        g_base[z][c][t] = ((const float4*)red)[t];
    }
}

// ---------------------------------------------------------------------------
// K2: per-z middle. grid = B, 512 threads.
//   (0) bulk-copy precomputed W12 from g_W12g into shared (L2-hot, coalesced)
//   (1) M[16][32]: gy-weighted reduce over c from g_base
//   (2) U coefficients -> SHARED (no global round-trip)
//   (3) V[a][slot] expansion coefficients (pre-scaled by 1/n) -> g_V
//   M rows: m=0: p0; m=1..3: p1[x]; m=4..6: gy[y]*p0; m=7..15: gy[y]*p1[x]
//   U layout: U0[0:32] | U1[32+x*32+i] | U2[128+y*32+i] | U3[224+(y*3+x)*32+i]
// ---------------------------------------------------------------------------
__global__ void __launch_bounds__(512, 1) k_middle(const float* __restrict__ geo,
                                                   const void* __restrict__ n_norm_ptr) {
    int z = blockIdx.x;
    int t = threadIdx.x;  // 512

    __shared__ float sW12[9 * 32 * 32];  // 36 KB: [yx][i][k]
    __shared__ float sM[16][32];         // 2 KB
    __shared__ float sU[512];            // 2 KB
    __shared__ float sgeo[3][NN];        // 1.5 KB

    if (t < NN * 3) {
        int c = t / 3, comp = t - c * 3;
        sgeo[comp][c] = geo[z * NN * 3 + t];
    }

    // (0) copy W12: 2304 float4 across 512 threads (coalesced, independent).
    {
        float4* s4 = (float4*)sW12;
        const float4* g4 = (const float4*)g_W12g;
        #pragma unroll
        for (int r = 0; r < 4; r++) s4[t + r * 512] = g4[t + r * 512];
        if (t < 2304 - 2048) s4[t + 2048] = g4[t + 2048];
    }

    // (1) gy-weighted reduce over c. One (m,k) slot per thread. Needs sgeo.
    __syncthreads();
    {
        int m = t >> 5;
        int k = t & 31;
        int b, y;
        if (m < 4)      { b = m;  y = -1; }
        else if (m < 7) { b = 0;  y = m - 4; }
        else            { int mm = m - 7; y = mm / 3; b = 1 + (mm - y * 3); }

        const float* base = (const float*)&g_base[z][0][0] + b * 32 + k;  // stride 128
        float s = 0.f;
        if (y < 0) {
            #pragma unroll 16
            for (int c = 0; c < NN; c++) s += base[c * 128];
        } else {
            const float* gy = &sgeo[y][0];
            #pragma unroll 16
            for (int c = 0; c < NN; c++) s = fmaf(base[c * 128], gy[c], s);
        }
        (&sM[0][0])[t] = s;
    }
    __syncthreads();

    // (2) U from shared. One output per thread -> sU.
    {
        float r = 0.f;
        if (t < 32) {
            int i = t;
            for (int yx = 0; yx < 9; yx++) {
                const float* w = &sW12[(yx * 32 + i) * 32];
                const float* m = &sM[7 + yx][0];
                #pragma unroll
                for (int k = 0; k < 32; k++) r = fmaf(w[k], m[k], r);
            }
        } else if (t < 128) {
            int x = (t - 32) >> 5, i = t & 31;
            for (int y = 0; y < 3; y++) {
                const float* w = &sW12[((y * 3 + x) * 32 + i) * 32];
                const float* m = &sM[4 + y][0];
                #pragma unroll
                for (int k = 0; k < 32; k++) r = fmaf(w[k], m[k], r);
            }
        } else if (t < 224) {
            int y = (t - 128) >> 5, i = t & 31;
            for (int x = 0; x < 3; x++) {
                const float* w = &sW12[((y * 3 + x) * 32 + i) * 32];
                const float* m = &sM[1 + x][0];
                #pragma unroll
                for (int k = 0; k < 32; k++) r = fmaf(w[k], m[k], r);
            }
        } else {
            int m3 = t - 224;
            int yx = m3 >> 5, i = m3 & 31;
            const float* w = &sW12[(yx * 32 + i) * 32];
            const float* m = &sM[0][0];
            #pragma unroll
            for (int k = 0; k < 32; k++) r = fmaf(w[k], m[k], r);
        }
        sU[t] = r;
    }
    __syncthreads();

    // (3) V expansion for all 128 a: 16384 outputs, 32 per thread, coalesced.
    float inv_n = 1.0f / load_scalar_f(n_norm_ptr);
    float* Vz = &g_V[z][0][0];
    for (int r = 0; r < 32; r++) {
        int idx = t + r * 512;
        int a = idx >> 7, slot = idx & 127;
        float ga0 = sgeo[0][a], ga1 = sgeo[1][a], ga2 = sgeo[2][a];
        float v;
        if (slot < 32) {
            int i = slot;
            v = sU[i] - (ga0 * sU[128 + i] + ga1 * sU[160 + i] + ga2 * sU[192 + i]);
        } else {
            int x = (slot - 32) >> 5, i = slot & 31;
            v = -sU[32 + x * 32 + i]
              + ga0 * sU[224 + (0 * 3 + x) * 32 + i]
              + ga1 * sU[224 + (1 * 3 + x) * 32 + i]
              + ga2 * sU[224 + (2 * 3 + x) * 32 + i];
        }
        Vz[idx] = inv_n * v;
    }
}

// ---------------------------------------------------------------------------
// K3: output expansion. grid = B*N (one block per (z,a)), 256 threads.
// out[z,a,b,i] = V0[i] + sum_x gb_x * V1[x,i]   (V precomputed in k_middle)
// Prologue is now just a 128-float L2-hot row load + geo staging.
// ---------------------------------------------------------------------------
__global__ void __launch_bounds__(256) k_expand(const float* __restrict__ geo,
                                                float* __restrict__ out) {
    int za = blockIdx.x;
    int z = za >> 7;
    int a = za & (NN - 1);
    int t = threadIdx.x;  // 256

    __shared__ float sV[128];
    __shared__ float sg[NN * 3];

    if (t < 128) sV[t] = g_V[z][a][t];
    if (t < NN * 3 - 256) sg[256 + t] = geo[z * 384 + 256 + t];
    sg[t] = geo[z * 384 + t];
    __syncthreads();

    int i4   = t & 7;    // which float4 of the 32-float output row
    int bgrp = t >> 3;   // 0..31

    const float4* sV4 = (const float4*)sV;
    float4 v0  = sV4[i4];
    float4 v10 = sV4[8 + i4], v11 = sV4[16 + i4], v12 = sV4[24 + i4];

    float4* ob4 = (float4*)(out + ((size_t)za << 12));
    #pragma unroll
    for (int it = 0; it < 4; it++) {
        int b = bgrp + it * 32;
        float gb0 = sg[b * 3 + 0], gb1 = sg[b * 3 + 1], gb2 = sg[b * 3 + 2];
        float4 v;
        v.x = fmaf(gb2, v12.x, fmaf(gb1, v11.x, fmaf(gb0, v10.x, v0.x)));
        v.y = fmaf(gb2, v12.y, fmaf(gb1, v11.y, fmaf(gb0, v10.y, v0.y)));
        v.z = fmaf(gb2, v12.z, fmaf(gb1, v11.z, fmaf(gb0, v10.z, v0.z)));
        v.w = fmaf(gb2, v12.w, fmaf(gb1, v11.w, fmaf(gb0, v10.w, v0.w)));
        ob4[b * 8 + i4] = v;
    }
}

// ---------------------------------------------------------------------------
// kernel_launch
// Inputs: features f32[4,128,128,32], geometry f32[4,128,3],
//         W1 f32[3,32,32], W2 f32[3,32,32], n_norm scalar.
// Output: f32[4,128,128,32].
// ---------------------------------------------------------------------------
extern "C" void kernel_launch(void* const* d_in, const int* in_sizes, int n_in,
                              void* d_out, int out_size) {
    const float* feat = (const float*)d_in[0];
    const float* geo  = (const float*)d_in[1];
    const float* W1   = (const float*)d_in[2];
    const float* W2   = (const float*)d_in[3];
    const void*  nrm  = (n_in > 4) ? d_in[4] : nullptr;
    float* out = (float*)d_out;

    k_partial<<<BZ * NN + 9, 256>>>(feat, geo, W1, W2);
    k_middle<<<BZ, 512>>>(geo, nrm);
    k_expand<<<BZ * NN, 256>>>(geo, out);
}

// round 13
// speedup vs baseline: 1.0868x; 1.0868x over previous
#include <cuda_runtime.h>
#include <cuda_bf16.h>
#include <cstdint>

// Problem shapes (fixed by setup_inputs): B=4, N=128, C_IN=C_OUT=32, X=3.
#define BZ 4
#define NN 128

// ---------------------------------------------------------------------------
// Scratch (no allocations allowed -> __device__ globals)
// ---------------------------------------------------------------------------
// Per-(z,c) BASE sums: row = 128 floats [b][k]: b=0: p0 = sum_d f;
// b=1..3: p1[x] = sum_d g[d,x]*f.
__device__ float4 g_base[BZ][NN][32];     // 256 KB
__device__ float  g_W12g[9 * 32 * 32];    // W12[yx][i][k] = sum_j W2[y,i,j]*W1[x,j,k]
__device__ float  g_U[BZ][512];           // U0[32] | U1[96] | U2[96] | U3[288]

// Robust scalar load: handles int32 or float32 encodings of n_norm.
__device__ __forceinline__ float load_scalar_f(const void* p) {
    int iv = *(const int*)p;
    int ex = (iv >> 23) & 0xFF;
    if (ex > 60 && ex < 200) return __int_as_float(iv);
    return (float)iv;
}

// ---------------------------------------------------------------------------
// K1: grid = BZ*NN + 9, 512 threads (r12 evidence: 256-thr version capped at
// ~28 warps/SM, 44% occ, 1.47 TB/s — widen to ~55 warps/SM).
//   blocks [0..511]: per-(z,c) base sums, 2 float4 loads/thread.
//   blocks [512..520]: W12[yx] = W2[y] @ W1[x] via smem staging (reg-light).
// Launch bounds cap regs at 42 so the rider path can't inflate the hot path.
// ---------------------------------------------------------------------------
__global__ void __launch_bounds__(512, 3) k_partial(const float* __restrict__ feat,
                                                    const float* __restrict__ geo,
                                                    const float* __restrict__ W1,
                                                    const float* __restrict__ W2) {
    int zc = blockIdx.x;
    int t = threadIdx.x;        // 512

    // ---- W12 rider blocks: stage weights in smem, then LDS-fed FMA chains ----
    if (zc >= BZ * NN) {
        __shared__ float sw1[1024];   // W1[x][j][k]
        __shared__ float sw2[1024];   // W2[y][i][j]
        int yx = zc - BZ * NN;        // 0..8
        int y = yx / 3, x = yx - y * 3;
        sw2[t]       = W2[y * 1024 + t];
        sw2[t + 512] = W2[y * 1024 + t + 512];
        sw1[t]       = W1[x * 1024 + t];
        sw1[t + 512] = W1[x * 1024 + t + 512];
        __syncthreads();
        #pragma unroll
        for (int r = 0; r < 2; r++) {
            int idx = t + r * 512;    // i*32 + k
            int i = idx >> 5, k = idx & 31;
            float acc = 0.f;
            #pragma unroll
            for (int j = 0; j < 32; j++) acc = fmaf(sw2[i * 32 + j], sw1[j * 32 + k], acc);
            g_W12g[yx * 1024 + idx] = acc;
        }
        return;
    }

    int z = zc >> 7;
    int kq   = t & 7;           // which float4 within the 32-float k-row
    int dgrp = t >> 3;          // 0..63

    __shared__ float  sgeo[3][NN];     // geo[z] transposed: [comp][d]
    __shared__ float4 smq[4][64][8];   // [comp][dgrp][kq], 32 KB
    __shared__ float  red[4][32];      // reduced sums [comp][k]

    if (t < NN * 3) {
        int d = t / 3, comp = t - d * 3;
        sgeo[comp][d] = geo[z * NN * 3 + t];
    }
    __syncthreads();

    const float4* f4 = (const float4*)(feat + ((size_t)zc << 12));
    float4 s0 = make_float4(0.f, 0.f, 0.f, 0.f);
    float4 sx = s0, sy = s0, sz2 = s0;

    #pragma unroll
    for (int it = 0; it < 2; it++) {
        int d = dgrp + it * 64;
        float4 f = f4[d * 8 + kq];
        float g0 = sgeo[0][d], g1 = sgeo[1][d], g2 = sgeo[2][d];
        s0.x += f.x;  s0.y += f.y;  s0.z += f.z;  s0.w += f.w;
        sx.x = fmaf(f.x, g0, sx.x);  sx.y = fmaf(f.y, g0, sx.y);
        sx.z = fmaf(f.z, g0, sx.z);  sx.w = fmaf(f.w, g0, sx.w);
        sy.x = fmaf(f.x, g1, sy.x);  sy.y = fmaf(f.y, g1, sy.y);
        sy.z = fmaf(f.z, g1, sy.z);  sy.w = fmaf(f.w, g1, sy.w);
        sz2.x = fmaf(f.x, g2, sz2.x);  sz2.y = fmaf(f.y, g2, sz2.y);
        sz2.z = fmaf(f.z, g2, sz2.z);  sz2.w = fmaf(f.w, g2, sz2.w);
    }

    smq[0][dgrp][kq] = s0;
    smq[1][dgrp][kq] = sx;
    smq[2][dgrp][kq] = sy;
    smq[3][dgrp][kq] = sz2;
    __syncthreads();

    // Reduce over 64 dgrps: threads t<128 -> (comp = t>>5, k = t&31).
    if (t < 128) {
        int comp = t >> 5;
        int k = t & 31;
        const float* p = (const float*)&smq[comp][0][0];  // 2048 floats
        float s = 0.f;
        #pragma unroll
        for (int dg = 0; dg < 64; dg++) s += p[dg * 32 + k];
        red[comp][k] = s;
    }
    __syncthreads();

    // Write the 128-float base row as 32 float4s (coalesced 512B).
    if (t < 32) {
        int c = zc & (NN - 1);
        g_base[z][c][t] = ((const float4*)red)[t];
    }
}

// ---------------------------------------------------------------------------
// K2: per-z middle (EXACT r11 version — best measured). grid = B, 512 threads.
//   (0) bulk-copy precomputed W12 from g_W12g into shared (L2-hot, coalesced)
//   (1) M[16][32]: gy-weighted reduce over c from g_base
//   (2) U coefficients from shared -> g_U
//   M rows: m=0: p0; m=1..3: p1[x]; m=4..6: gy[y]*p0; m=7..15: gy[y]*p1[x]
// ---------------------------------------------------------------------------
__global__ void __launch_bounds__(512, 1) k_middle(const float* __restrict__ geo) {
    int z = blockIdx.x;
    int t = threadIdx.x;  // 512

    __shared__ float sW12[9 * 32 * 32];  // 36 KB: [yx][i][k]
    __shared__ float sM[16][32];         // 2 KB
    __shared__ float sgeo[3][NN];        // 1.5 KB

    if (t < NN * 3) {
        int c = t / 3, comp = t - c * 3;
        sgeo[comp][c] = geo[z * NN * 3 + t];
    }

    // (0) copy W12: 2304 float4 across 512 threads (coalesced, independent).
    {
        float4* s4 = (float4*)sW12;
        const float4* g4 = (const float4*)g_W12g;
        #pragma unroll
        for (int r = 0; r < 4; r++) s4[t + r * 512] = g4[t + r * 512];
        if (t < 2304 - 2048) s4[t + 2048] = g4[t + 2048];
    }

    // (1) gy-weighted reduce over c. One (m,k) slot per thread. Needs sgeo.
    __syncthreads();
    {
        int m = t >> 5;
        int k = t & 31;
        int b, y;
        if (m < 4)      { b = m;  y = -1; }
        else if (m < 7) { b = 0;  y = m - 4; }
        else            { int mm = m - 7; y = mm / 3; b = 1 + (mm - y * 3); }

        const float* base = (const float*)&g_base[z][0][0] + b * 32 + k;  // stride 128
        float s = 0.f;
        if (y < 0) {
            #pragma unroll 16
            for (int c = 0; c < NN; c++) s += base[c * 128];
        } else {
            const float* gy = &sgeo[y][0];
            #pragma unroll 16
            for (int c = 0; c < NN; c++) s = fmaf(base[c * 128], gy[c], s);
        }
        (&sM[0][0])[t] = s;
    }
    __syncthreads();

    // (2) U from shared. One output per thread.
    float r = 0.f;
    if (t < 32) {
        int i = t;
        for (int yx = 0; yx < 9; yx++) {
            const float* w = &sW12[(yx * 32 + i) * 32];
            const float* m = &sM[7 + yx][0];
            #pragma unroll
            for (int k = 0; k < 32; k++) r = fmaf(w[k], m[k], r);
        }
    } else if (t < 128) {
        int x = (t - 32) >> 5, i = t & 31;
        for (int y = 0; y < 3; y++) {
            const float* w = &sW12[((y * 3 + x) * 32 + i) * 32];
            const float* m = &sM[4 + y][0];
            #pragma unroll
            for (int k = 0; k < 32; k++) r = fmaf(w[k], m[k], r);
        }
    } else if (t < 224) {
        int y = (t - 128) >> 5, i = t & 31;
        for (int x = 0; x < 3; x++) {
            const float* w = &sW12[((y * 3 + x) * 32 + i) * 32];
            const float* m = &sM[1 + x][0];
            #pragma unroll
            for (int k = 0; k < 32; k++) r = fmaf(w[k], m[k], r);
        }
    } else {
        int m3 = t - 224;
        int yx = m3 >> 5, i = m3 & 31;
        const float* w = &sW12[(yx * 32 + i) * 32];
        const float* m = &sM[0][0];
        #pragma unroll
        for (int k = 0; k < 32; k++) r = fmaf(w[k], m[k], r);
    }
    g_U[z][t] = r;
}

// ---------------------------------------------------------------------------
// K3: output expansion (EXACT r11 version — best measured). grid = B*N, 256 thr.
// out[z,a,b,i] = V0[i] + sum_x gb_x * V1[x,i]   (V pre-scaled by 1/n)
// ---------------------------------------------------------------------------
__global__ void __launch_bounds__(256) k_expand(const float* __restrict__ geo,
                                                float* __restrict__ out,
                                                const void* __restrict__ n_norm_ptr) {
    int za = blockIdx.x;
    int z = za >> 7;
    int a = za & (NN - 1);
    int t = threadIdx.x;  // 256

    __shared__ float  sU[512];
    __shared__ float  sg[NN * 3];
    __shared__ float4 V0q[8];        // V0[32]
    __shared__ float4 V1q[3][8];     // V1[3][32]

    sU[t] = g_U[z][t];
    sU[t + 256] = g_U[z][t + 256];
    for (int idx = t; idx < NN * 3; idx += 256) sg[idx] = geo[z * NN * 3 + idx];
    __syncthreads();

    float inv_n = 1.0f / load_scalar_f(n_norm_ptr);
    float ga0 = sg[a * 3 + 0], ga1 = sg[a * 3 + 1], ga2 = sg[a * 3 + 2];

    if (t < 32) {
        int i = t;
        ((float*)V0q)[i] = inv_n *
            (sU[i] - (ga0 * sU[128 + i] + ga1 * sU[160 + i] + ga2 * sU[192 + i]));
    } else if (t < 128) {
        int x = (t - 32) >> 5, i = t & 31;
        ((float*)V1q)[x * 32 + i] = inv_n *
            (-sU[32 + x * 32 + i]
             + ga0 * sU[224 + (0 * 3 + x) * 32 + i]
             + ga1 * sU[224 + (1 * 3 + x) * 32 + i]
             + ga2 * sU[224 + (2 * 3 + x) * 32 + i]);
    }
    __syncthreads();

    int i4   = t & 7;    // which float4 of the 32-float output row
    int bgrp = t >> 3;   // 0..31

    float4 v0  = V0q[i4];
    float4 v10 = V1q[0][i4], v11 = V1q[1][i4], v12 = V1q[2][i4];

    float4* ob4 = (float4*)(out + ((size_t)za << 12));
    #pragma unroll
    for (int it = 0; it < 4; it++) {
        int b = bgrp + it * 32;
        float gb0 = sg[b * 3 + 0], gb1 = sg[b * 3 + 1], gb2 = sg[b * 3 + 2];
        float4 v;
        v.x = fmaf(gb2, v12.x, fmaf(gb1, v11.x, fmaf(gb0, v10.x, v0.x)));
        v.y = fmaf(gb2, v12.y, fmaf(gb1, v11.y, fmaf(gb0, v10.y, v0.y)));
        v.z = fmaf(gb2, v12.z, fmaf(gb1, v11.z, fmaf(gb0, v10.z, v0.z)));
        v.w = fmaf(gb2, v12.w, fmaf(gb1, v11.w, fmaf(gb0, v10.w, v0.w)));
        ob4[b * 8 + i4] = v;
    }
}

// ---------------------------------------------------------------------------
// kernel_launch
// Inputs: features f32[4,128,128,32], geometry f32[4,128,3],
//         W1 f32[3,32,32], W2 f32[3,32,32], n_norm scalar.
// Output: f32[4,128,128,32].
// ---------------------------------------------------------------------------
extern "C" void kernel_launch(void* const* d_in, const int* in_sizes, int n_in,
                              void* d_out, int out_size) {
    const float* feat = (const float*)d_in[0];
    const float* geo  = (const float*)d_in[1];
    const float* W1   = (const float*)d_in[2];
    const float* W2   = (const float*)d_in[3];
    const void*  nrm  = (n_in > 4) ? d_in[4] : nullptr;
    float* out = (float*)d_out;

    k_partial<<<BZ * NN + 9, 512>>>(feat, geo, W1, W2);
    k_middle<<<BZ, 512>>>(geo);
    k_expand<<<BZ * NN, 256>>>(geo, out, nrm);
}

// round 14
// speedup vs baseline: 1.1882x; 1.0933x over previous
#include <cuda_runtime.h>
#include <cuda_bf16.h>
#include <cstdint>

// Problem shapes (fixed by setup_inputs): B=4, N=128, C_IN=C_OUT=32, X=3.
#define BZ 4
#define NN 128

// ---------------------------------------------------------------------------
// Scratch (no allocations allowed -> __device__ globals)
// ---------------------------------------------------------------------------
// Per-(z,c) BASE sums: row = 128 floats [b][k]: b=0: p0 = sum_d f;
// b=1..3: p1[x] = sum_d g[d,x]*f.
__device__ float4 g_base[BZ][NN][32];     // 256 KB
__device__ float  g_W12g[9 * 32 * 32];    // W12[yx][i][k] = sum_j W2[y,i,j]*W1[x,j,k]
__device__ float  g_U[BZ][512];           // U0[32] | U1[96] | U2[96] | U3[288]

// Robust scalar load: handles int32 or float32 encodings of n_norm.
__device__ __forceinline__ float load_scalar_f(const void* p) {
    int iv = *(const int*)p;
    int ex = (iv >> 23) & 0xFF;
    if (ex > 60 && ex < 200) return __int_as_float(iv);
    return (float)iv;
}

// ---------------------------------------------------------------------------
// K1: grid = BZ*NN + 9, 256 threads (EXACT r11 shape — measured optimum at
// 5.7-5.9us; both 512-thr and reordered-load variants measured slower).
//   blocks [0..511]: per-(z,c) base sums.
//   blocks [512..520]: W12[yx] = W2[y] @ W1[x] via smem staging (reg-light).
// ---------------------------------------------------------------------------
__global__ void __launch_bounds__(256, 6) k_partial(const float* __restrict__ feat,
                                                    const float* __restrict__ geo,
                                                    const float* __restrict__ W1,
                                                    const float* __restrict__ W2) {
    int zc = blockIdx.x;
    int t = threadIdx.x;        // 256

    // ---- W12 rider blocks: stage weights in smem, then LDS-fed FMA chains ----
    if (zc >= BZ * NN) {
        __shared__ float sw1[1024];   // W1[x][j][k]
        __shared__ float sw2[1024];   // W2[y][i][j]
        int yx = zc - BZ * NN;        // 0..8
        int y = yx / 3, x = yx - y * 3;
        #pragma unroll
        for (int r = 0; r < 4; r++) {
            sw2[t + r * 256] = W2[y * 1024 + t + r * 256];
            sw1[t + r * 256] = W1[x * 1024 + t + r * 256];
        }
        __syncthreads();
        #pragma unroll
        for (int r = 0; r < 4; r++) {
            int idx = t + r * 256;    // i*32 + k
            int i = idx >> 5, k = idx & 31;
            float acc = 0.f;
            #pragma unroll
            for (int j = 0; j < 32; j++) acc = fmaf(sw2[i * 32 + j], sw1[j * 32 + k], acc);
            g_W12g[yx * 1024 + idx] = acc;
        }
        return;
    }

    int z = zc >> 7;
    int kq   = t & 7;           // which float4 within the 32-float k-row
    int dgrp = t >> 3;          // 0..31

    __shared__ float  sgeo[3][NN];     // geo[z] transposed: [comp][d]
    __shared__ float4 smq[4][32][8];   // [comp][dgrp][kq], 16 KB
    __shared__ float  red[4][32];      // reduced sums [comp][k]

    if (t < NN * 3) {
        int d = t / 3, comp = t - d * 3;
        sgeo[comp][d] = geo[z * NN * 3 + t];
    }
    if (t + 256 < NN * 3) {
        int idx = t + 256;
        int d = idx / 3, comp = idx - d * 3;
        sgeo[comp][d] = geo[z * NN * 3 + idx];
    }
    __syncthreads();

    const float4* f4 = (const float4*)(feat + ((size_t)zc << 12));
    float4 s0 = make_float4(0.f, 0.f, 0.f, 0.f);
    float4 sx = s0, sy = s0, sz2 = s0;

    #pragma unroll
    for (int it = 0; it < 4; it++) {
        int d = dgrp + it * 32;
        float4 f = f4[d * 8 + kq];
        float g0 = sgeo[0][d], g1 = sgeo[1][d], g2 = sgeo[2][d];
        s0.x += f.x;  s0.y += f.y;  s0.z += f.z;  s0.w += f.w;
        sx.x = fmaf(f.x, g0, sx.x);  sx.y = fmaf(f.y, g0, sx.y);
        sx.z = fmaf(f.z, g0, sx.z);  sx.w = fmaf(f.w, g0, sx.w);
        sy.x = fmaf(f.x, g1, sy.x);  sy.y = fmaf(f.y, g1, sy.y);
        sy.z = fmaf(f.z, g1, sy.z);  sy.w = fmaf(f.w, g1, sy.w);
        sz2.x = fmaf(f.x, g2, sz2.x);  sz2.y = fmaf(f.y, g2, sz2.y);
        sz2.z = fmaf(f.z, g2, sz2.z);  sz2.w = fmaf(f.w, g2, sz2.w);
    }

    smq[0][dgrp][kq] = s0;
    smq[1][dgrp][kq] = sx;
    smq[2][dgrp][kq] = sy;
    smq[3][dgrp][kq] = sz2;
    __syncthreads();

    // Reduce over 32 dgrps: threads t<128 -> (comp = t>>5, k = t&31).
    if (t < 128) {
        int comp = t >> 5;
        int k = t & 31;
        const float* p = (const float*)&smq[comp][0][0];  // 1024 floats
        float s = 0.f;
        #pragma unroll
        for (int dg = 0; dg < 32; dg++) s += p[dg * 32 + k];
        red[comp][k] = s;
    }
    __syncthreads();

    // Write the 128-float base row as 32 float4s (coalesced 512B).
    if (t < 32) {
        int c = zc & (NN - 1);
        g_base[z][c][t] = ((const float4*)red)[t];
    }
}

// ---------------------------------------------------------------------------
// K2: per-z middle (r11 body + PDL). grid = B, 512 threads.
// PDL: geo staging runs before cudaGridDependencySynchronize(); everything
// touching g_W12g / g_base comes after.
// ---------------------------------------------------------------------------
__global__ void __launch_bounds__(512, 1) k_middle(const float* __restrict__ geo) {
    int z = blockIdx.x;
    int t = threadIdx.x;  // 512

    __shared__ float sW12[9 * 32 * 32];  // 36 KB: [yx][i][k]
    __shared__ float sM[16][32];         // 2 KB
    __shared__ float sgeo[3][NN];        // 1.5 KB

    // Independent prologue: geo staging (input only).
    if (t < NN * 3) {
        int c = t / 3, comp = t - c * 3;
        sgeo[comp][c] = geo[z * NN * 3 + t];
    }

    // Wait for k_partial grid (g_base + g_W12g) to complete.
    cudaGridDependencySynchronize();

    // (0) copy W12: 2304 float4 across 512 threads (coalesced, independent).
    {
        float4* s4 = (float4*)sW12;
        const float4* g4 = (const float4*)g_W12g;
        #pragma unroll
        for (int r = 0; r < 4; r++) s4[t + r * 512] = g4[t + r * 512];
        if (t < 2304 - 2048) s4[t + 2048] = g4[t + 2048];
    }

    // (1) gy-weighted reduce over c. One (m,k) slot per thread. Needs sgeo.
    __syncthreads();
    {
        int m = t >> 5;
        int k = t & 31;
        int b, y;
        if (m < 4)      { b = m;  y = -1; }
        else if (m < 7) { b = 0;  y = m - 4; }
        else            { int mm = m - 7; y = mm / 3; b = 1 + (mm - y * 3); }

        const float* base = (const float*)&g_base[z][0][0] + b * 32 + k;  // stride 128
        float s = 0.f;
        if (y < 0) {
            #pragma unroll 16
            for (int c = 0; c < NN; c++) s += base[c * 128];
        } else {
            const float* gy = &sgeo[y][0];
            #pragma unroll 16
            for (int c = 0; c < NN; c++) s = fmaf(base[c * 128], gy[c], s);
        }
        (&sM[0][0])[t] = s;
    }
    __syncthreads();

    // (2) U from shared. One output per thread.
    float r = 0.f;
    if (t < 32) {
        int i = t;
        for (int yx = 0; yx < 9; yx++) {
            const float* w = &sW12[(yx * 32 + i) * 32];
            const float* m = &sM[7 + yx][0];
            #pragma unroll
            for (int k = 0; k < 32; k++) r = fmaf(w[k], m[k], r);
        }
    } else if (t < 128) {
        int x = (t - 32) >> 5, i = t & 31;
        for (int y = 0; y < 3; y++) {
            const float* w = &sW12[((y * 3 + x) * 32 + i) * 32];
            const float* m = &sM[4 + y][0];
            #pragma unroll
            for (int k = 0; k < 32; k++) r = fmaf(w[k], m[k], r);
        }
    } else if (t < 224) {
        int y = (t - 128) >> 5, i = t & 31;
        for (int x = 0; x < 3; x++) {
            const float* w = &sW12[((y * 3 + x) * 32 + i) * 32];
            const float* m = &sM[1 + x][0];
            #pragma unroll
            for (int k = 0; k < 32; k++) r = fmaf(w[k], m[k], r);
        }
    } else {
        int m3 = t - 224;
        int yx = m3 >> 5, i = m3 & 31;
        const float* w = &sW12[(yx * 32 + i) * 32];
        const float* m = &sM[0][0];
        #pragma unroll
        for (int k = 0; k < 32; k++) r = fmaf(w[k], m[k], r);
    }
    g_U[z][t] = r;
}

// ---------------------------------------------------------------------------
// K3: output expansion (r11 body + PDL). grid = B*N, 256 thr.
// Geo staging before gridDepSync; g_U load after.
// ---------------------------------------------------------------------------
__global__ void __launch_bounds__(256) k_expand(const float* __restrict__ geo,
                                                float* __restrict__ out,
                                                const void* __restrict__ n_norm_ptr) {
    int za = blockIdx.x;
    int z = za >> 7;
    int a = za & (NN - 1);
    int t = threadIdx.x;  // 256

    __shared__ float  sU[512];
    __shared__ float  sg[NN * 3];
    __shared__ float4 V0q[8];        // V0[32]
    __shared__ float4 V1q[3][8];     // V1[3][32]

    // Independent prologue: geo staging (input only).
    for (int idx = t; idx < NN * 3; idx += 256) sg[idx] = geo[z * NN * 3 + idx];

    // Wait for k_middle grid (g_U) to complete.
    cudaGridDependencySynchronize();

    sU[t] = g_U[z][t];
    sU[t + 256] = g_U[z][t + 256];
    __syncthreads();

    float inv_n = 1.0f / load_scalar_f(n_norm_ptr);
    float ga0 = sg[a * 3 + 0], ga1 = sg[a * 3 + 1], ga2 = sg[a * 3 + 2];

    if (t < 32) {
        int i = t;
        ((float*)V0q)[i] = inv_n *
            (sU[i] - (ga0 * sU[128 + i] + ga1 * sU[160 + i] + ga2 * sU[192 + i]));
    } else if (t < 128) {
        int x = (t - 32) >> 5, i = t & 31;
        ((float*)V1q)[x * 32 + i] = inv_n *
            (-sU[32 + x * 32 + i]
             + ga0 * sU[224 + (0 * 3 + x) * 32 + i]
             + ga1 * sU[224 + (1 * 3 + x) * 32 + i]
             + ga2 * sU[224 + (2 * 3 + x) * 32 + i]);
    }
    __syncthreads();

    int i4   = t & 7;    // which float4 of the 32-float output row
    int bgrp = t >> 3;   // 0..31

    float4 v0  = V0q[i4];
    float4 v10 = V1q[0][i4], v11 = V1q[1][i4], v12 = V1q[2][i4];

    float4* ob4 = (float4*)(out + ((size_t)za << 12));
    #pragma unroll
    for (int it = 0; it < 4; it++) {
        int b = bgrp + it * 32;
        float gb0 = sg[b * 3 + 0], gb1 = sg[b * 3 + 1], gb2 = sg[b * 3 + 2];
        float4 v;
        v.x = fmaf(gb2, v12.x, fmaf(gb1, v11.x, fmaf(gb0, v10.x, v0.x)));
        v.y = fmaf(gb2, v12.y, fmaf(gb1, v11.y, fmaf(gb0, v10.y, v0.y)));
        v.z = fmaf(gb2, v12.z, fmaf(gb1, v11.z, fmaf(gb0, v10.z, v0.z)));
        v.w = fmaf(gb2, v12.w, fmaf(gb1, v11.w, fmaf(gb0, v10.w, v0.w)));
        ob4[b * 8 + i4] = v;
    }
}

// ---------------------------------------------------------------------------
// kernel_launch — k_middle and k_expand launched with PDL
// (programmatic stream serialization) to hide launch gaps.
// ---------------------------------------------------------------------------
extern "C" void kernel_launch(void* const* d_in, const int* in_sizes, int n_in,
                              void* d_out, int out_size) {
    const float* feat = (const float*)d_in[0];
    const float* geo  = (const float*)d_in[1];
    const float* W1   = (const float*)d_in[2];
    const float* W2   = (const float*)d_in[3];
    const void*  nrm  = (n_in > 4) ? d_in[4] : nullptr;
    float* out = (float*)d_out;

    k_partial<<<BZ * NN + 9, 256>>>(feat, geo, W1, W2);

    cudaLaunchAttribute attr[1];
    attr[0].id = cudaLaunchAttributeProgrammaticStreamSerialization;
    attr[0].val.programmaticStreamSerializationAllowed = 1;

    {
        cudaLaunchConfig_t cfg = {};
        cfg.gridDim = dim3(BZ);
        cfg.blockDim = dim3(512);
        cfg.attrs = attr;
        cfg.numAttrs = 1;
        cudaLaunchKernelEx(&cfg, k_middle, geo);
    }
    {
        cudaLaunchConfig_t cfg = {};
        cfg.gridDim = dim3(BZ * NN);
        cfg.blockDim = dim3(256);
        cfg.attrs = attr;
        cfg.numAttrs = 1;
        cudaLaunchKernelEx(&cfg, k_expand, geo, out, (const void*)nrm);
    }
}

// round 15
// speedup vs baseline: 1.1938x; 1.0047x over previous
#include <cuda_runtime.h>
#include <cuda_bf16.h>
#include <cstdint>

// Problem shapes (fixed by setup_inputs): B=4, N=128, C_IN=C_OUT=32, X=3.
#define BZ 4
#define NN 128

// ---------------------------------------------------------------------------
// Scratch (no allocations allowed -> __device__ globals)
// ---------------------------------------------------------------------------
// Per-(z,c) BASE sums: row = 128 floats [b][k]: b=0: p0 = sum_d f;
// b=1..3: p1[x] = sum_d g[d,x]*f.
__device__ float4 g_base[BZ][NN][32];     // 256 KB
__device__ float  g_W12g[9 * 32 * 32];    // W12[yx][i][k] = sum_j W2[y,i,j]*W1[x,j,k]
__device__ float  g_U[BZ][512];           // U0[32] | U1[96] | U2[96] | U3[288]

// Robust scalar load: handles int32 or float32 encodings of n_norm.
__device__ __forceinline__ float load_scalar_f(const void* p) {
    int iv = *(const int*)p;
    int ex = (iv >> 23) & 0xFF;
    if (ex > 60 && ex < 200) return __int_as_float(iv);
    return (float)iv;
}

// ---------------------------------------------------------------------------
// K1: grid = BZ*NN/2 + 9 = 265, 256 threads. TWO c-rows per block:
// geo staged once per 2 rows, 8 independent float4 loads per thread.
//   blocks [0..255]: base sums for c-rows {2c, 2c+1}.
//   blocks [256..264]: W12[yx] = W2[y] @ W1[x] via smem staging (reg-light).
// ---------------------------------------------------------------------------
__global__ void __launch_bounds__(256, 4) k_partial(const float* __restrict__ feat,
                                                    const float* __restrict__ geo,
                                                    const float* __restrict__ W1,
                                                    const float* __restrict__ W2) {
    int blk = blockIdx.x;
    int t = threadIdx.x;        // 256

    // ---- W12 rider blocks: stage weights in smem, then LDS-fed FMA chains ----
    if (blk >= BZ * NN / 2) {
        __shared__ float sw1[1024];   // W1[x][j][k]
        __shared__ float sw2[1024];   // W2[y][i][j]
        int yx = blk - BZ * NN / 2;   // 0..8
        int y = yx / 3, x = yx - y * 3;
        #pragma unroll
        for (int r = 0; r < 4; r++) {
            sw2[t + r * 256] = W2[y * 1024 + t + r * 256];
            sw1[t + r * 256] = W1[x * 1024 + t + r * 256];
        }
        __syncthreads();
        #pragma unroll
        for (int r = 0; r < 4; r++) {
            int idx = t + r * 256;    // i*32 + k
            int i = idx >> 5, k = idx & 31;
            float acc = 0.f;
            #pragma unroll
            for (int j = 0; j < 32; j++) acc = fmaf(sw2[i * 32 + j], sw1[j * 32 + k], acc);
            g_W12g[yx * 1024 + idx] = acc;
        }
        return;
    }

    int z  = blk >> 6;          // 64 c-pairs per z
    int c0 = (blk & 63) * 2;    // first of the two c rows
    int kq   = t & 7;           // which float4 within the 32-float k-row
    int dgrp = t >> 3;          // 0..31

    __shared__ float  sgeo[3][NN];     // geo[z] transposed: [comp][d]
    __shared__ float4 smq[4][32][8];   // [comp][dgrp][kq], 16 KB
    __shared__ float  red[2][4][32];   // reduced sums per row [row][comp][k]

    if (t < NN * 3) {
        int d = t / 3, comp = t - d * 3;
        sgeo[comp][d] = geo[z * NN * 3 + t];
    }
    if (t + 256 < NN * 3) {
        int idx = t + 256;
        int d = idx / 3, comp = idx - d * 3;
        sgeo[comp][d] = geo[z * NN * 3 + idx];
    }
    __syncthreads();

    const float4* fA = (const float4*)(feat + ((size_t)(z * NN + c0) << 12));
    const float4* fB = fA + 1024;   // next c row (4096 floats)

    float4 zero = make_float4(0.f, 0.f, 0.f, 0.f);
    float4 a0 = zero, a1 = zero, a2 = zero, a3 = zero;   // row c0
    float4 b0 = zero, b1 = zero, b2 = zero, b3 = zero;   // row c0+1

    #pragma unroll
    for (int it = 0; it < 4; it++) {
        int d = dgrp + it * 32;
        float4 fa = fA[d * 8 + kq];
        float4 fb = fB[d * 8 + kq];
        float g0 = sgeo[0][d], g1 = sgeo[1][d], g2 = sgeo[2][d];
        a0.x += fa.x;  a0.y += fa.y;  a0.z += fa.z;  a0.w += fa.w;
        a1.x = fmaf(fa.x, g0, a1.x);  a1.y = fmaf(fa.y, g0, a1.y);
        a1.z = fmaf(fa.z, g0, a1.z);  a1.w = fmaf(fa.w, g0, a1.w);
        a2.x = fmaf(fa.x, g1, a2.x);  a2.y = fmaf(fa.y, g1, a2.y);
        a2.z = fmaf(fa.z, g1, a2.z);  a2.w = fmaf(fa.w, g1, a2.w);
        a3.x = fmaf(fa.x, g2, a3.x);  a3.y = fmaf(fa.y, g2, a3.y);
        a3.z = fmaf(fa.z, g2, a3.z);  a3.w = fmaf(fa.w, g2, a3.w);
        b0.x += fb.x;  b0.y += fb.y;  b0.z += fb.z;  b0.w += fb.w;
        b1.x = fmaf(fb.x, g0, b1.x);  b1.y = fmaf(fb.y, g0, b1.y);
        b1.z = fmaf(fb.z, g0, b1.z);  b1.w = fmaf(fb.w, g0, b1.w);
        b2.x = fmaf(fb.x, g1, b2.x);  b2.y = fmaf(fb.y, g1, b2.y);
        b2.z = fmaf(fb.z, g1, b2.z);  b2.w = fmaf(fb.w, g1, b2.w);
        b3.x = fmaf(fb.x, g2, b3.x);  b3.y = fmaf(fb.y, g2, b3.y);
        b3.z = fmaf(fb.z, g2, b3.z);  b3.w = fmaf(fb.w, g2, b3.w);
    }

    // Reduce row c0.
    smq[0][dgrp][kq] = a0;
    smq[1][dgrp][kq] = a1;
    smq[2][dgrp][kq] = a2;
    smq[3][dgrp][kq] = a3;
    __syncthreads();
    if (t < 128) {
        int comp = t >> 5;
        int k = t & 31;
        const float* p = (const float*)&smq[comp][0][0];  // 1024 floats
        float s = 0.f;
        #pragma unroll
        for (int dg = 0; dg < 32; dg++) s += p[dg * 32 + k];
        red[0][comp][k] = s;
    }
    __syncthreads();

    // Reduce row c0+1 (reuse smq).
    smq[0][dgrp][kq] = b0;
    smq[1][dgrp][kq] = b1;
    smq[2][dgrp][kq] = b2;
    smq[3][dgrp][kq] = b3;
    __syncthreads();
    if (t < 128) {
        int comp = t >> 5;
        int k = t & 31;
        const float* p = (const float*)&smq[comp][0][0];
        float s = 0.f;
        #pragma unroll
        for (int dg = 0; dg < 32; dg++) s += p[dg * 32 + k];
        red[1][comp][k] = s;
    }
    __syncthreads();

    // Write both base rows (64 float4, coalesced).
    if (t < 64) {
        int row = t >> 5;         // 0 or 1
        int q = t & 31;
        g_base[z][c0 + row][q] = ((const float4*)&red[row][0][0])[q];
    }
}

// ---------------------------------------------------------------------------
// K2: per-z middle (r11 body + PDL). grid = B, 512 threads.
// ---------------------------------------------------------------------------
__global__ void __launch_bounds__(512, 1) k_middle(const float* __restrict__ geo) {
    int z = blockIdx.x;
    int t = threadIdx.x;  // 512

    __shared__ float sW12[9 * 32 * 32];  // 36 KB: [yx][i][k]
    __shared__ float sM[16][32];         // 2 KB
    __shared__ float sgeo[3][NN];        // 1.5 KB

    // Independent prologue: geo staging (input only).
    if (t < NN * 3) {
        int c = t / 3, comp = t - c * 3;
        sgeo[comp][c] = geo[z * NN * 3 + t];
    }

    // Wait for k_partial grid (g_base + g_W12g) to complete.
    cudaGridDependencySynchronize();

    // (0) copy W12: 2304 float4 across 512 threads (coalesced, independent).
    {
        float4* s4 = (float4*)sW12;
        const float4* g4 = (const float4*)g_W12g;
        #pragma unroll
        for (int r = 0; r < 4; r++) s4[t + r * 512] = g4[t + r * 512];
        if (t < 2304 - 2048) s4[t + 2048] = g4[t + 2048];
    }

    // (1) gy-weighted reduce over c. One (m,k) slot per thread. Needs sgeo.
    __syncthreads();
    {
        int m = t >> 5;
        int k = t & 31;
        int b, y;
        if (m < 4)      { b = m;  y = -1; }
        else if (m < 7) { b = 0;  y = m - 4; }
        else            { int mm = m - 7; y = mm / 3; b = 1 + (mm - y * 3); }

        const float* base = (const float*)&g_base[z][0][0] + b * 32 + k;  // stride 128
        float s = 0.f;
        if (y < 0) {
            #pragma unroll 16
            for (int c = 0; c < NN; c++) s += base[c * 128];
        } else {
            const float* gy = &sgeo[y][0];
            #pragma unroll 16
            for (int c = 0; c < NN; c++) s = fmaf(base[c * 128], gy[c], s);
        }
        (&sM[0][0])[t] = s;
    }
    __syncthreads();

    // (2) U from shared. One output per thread.
    float r = 0.f;
    if (t < 32) {
        int i = t;
        for (int yx = 0; yx < 9; yx++) {
            const float* w = &sW12[(yx * 32 + i) * 32];
            const float* m = &sM[7 + yx][0];
            #pragma unroll
            for (int k = 0; k < 32; k++) r = fmaf(w[k], m[k], r);
        }
    } else if (t < 128) {
        int x = (t - 32) >> 5, i = t & 31;
        for (int y = 0; y < 3; y++) {
            const float* w = &sW12[((y * 3 + x) * 32 + i) * 32];
            const float* m = &sM[4 + y][0];
            #pragma unroll
            for (int k = 0; k < 32; k++) r = fmaf(w[k], m[k], r);
        }
    } else if (t < 224) {
        int y = (t - 128) >> 5, i = t & 31;
        for (int x = 0; x < 3; x++) {
            const float* w = &sW12[((y * 3 + x) * 32 + i) * 32];
            const float* m = &sM[1 + x][0];
            #pragma unroll
            for (int k = 0; k < 32; k++) r = fmaf(w[k], m[k], r);
        }
    } else {
        int m3 = t - 224;
        int yx = m3 >> 5, i = m3 & 31;
        const float* w = &sW12[(yx * 32 + i) * 32];
        const float* m = &sM[0][0];
        #pragma unroll
        for (int k = 0; k < 32; k++) r = fmaf(w[k], m[k], r);
    }
    g_U[z][t] = r;
}

// ---------------------------------------------------------------------------
// K3: output expansion. grid = BZ*NN/2 = 256, 256 threads. TWO a-rows per
// block: sU + geo staged once; V computed by ALL 256 threads (2 rows x 128
// slots); 8 float4 stores per thread.
// ---------------------------------------------------------------------------
__global__ void __launch_bounds__(256) k_expand(const float* __restrict__ geo,
                                                float* __restrict__ out,
                                                const void* __restrict__ n_norm_ptr) {
    int blk = blockIdx.x;
    int z  = blk >> 6;
    int a0 = (blk & 63) * 2;
    int t = threadIdx.x;  // 256

    __shared__ float sU[512];
    __shared__ float sg[NN * 3];
    __shared__ float sV[2][128];   // [row][slot]: V0[0:32] | V1[x*32+i + 32]

    // Independent prologue: geo staging (input only).
    for (int idx = t; idx < NN * 3; idx += 256) sg[idx] = geo[z * NN * 3 + idx];

    // Wait for k_middle grid (g_U) to complete.
    cudaGridDependencySynchronize();

    sU[t] = g_U[z][t];
    sU[t + 256] = g_U[z][t + 256];
    __syncthreads();

    float inv_n = 1.0f / load_scalar_f(n_norm_ptr);

    // V for both rows: 256 slots = 2 rows x 128.
    {
        int row  = t >> 7;          // 0 or 1
        int slot = t & 127;
        int a = a0 + row;
        float ga0 = sg[a * 3 + 0], ga1 = sg[a * 3 + 1], ga2 = sg[a * 3 + 2];
        float v;
        if (slot < 32) {
            int i = slot;
            v = sU[i] - (ga0 * sU[128 + i] + ga1 * sU[160 + i] + ga2 * sU[192 + i]);
        } else {
            int x = (slot - 32) >> 5, i = slot & 31;
            v = -sU[32 + x * 32 + i]
              + ga0 * sU[224 + (0 * 3 + x) * 32 + i]
              + ga1 * sU[224 + (1 * 3 + x) * 32 + i]
              + ga2 * sU[224 + (2 * 3 + x) * 32 + i];
        }
        sV[row][slot] = inv_n * v;
    }
    __syncthreads();

    int i4   = t & 7;    // which float4 of the 32-float output row
    int bgrp = t >> 3;   // 0..31

    const float4* sV0 = (const float4*)&sV[0][0];
    const float4* sV1 = (const float4*)&sV[1][0];
    float4 p0  = sV0[i4],     q0  = sV1[i4];
    float4 p10 = sV0[8 + i4], q10 = sV1[8 + i4];
    float4 p11 = sV0[16 + i4], q11 = sV1[16 + i4];
    float4 p12 = sV0[24 + i4], q12 = sV1[24 + i4];

    float4* oA = (float4*)(out + ((size_t)(z * NN + a0) << 12));
    float4* oB = oA + 1024;
    #pragma unroll
    for (int it = 0; it < 4; it++) {
        int b = bgrp + it * 32;
        float gb0 = sg[b * 3 + 0], gb1 = sg[b * 3 + 1], gb2 = sg[b * 3 + 2];
        float4 va, vb;
        va.x = fmaf(gb2, p12.x, fmaf(gb1, p11.x, fmaf(gb0, p10.x, p0.x)));
        va.y = fmaf(gb2, p12.y, fmaf(gb1, p11.y, fmaf(gb0, p10.y, p0.y)));
        va.z = fmaf(gb2, p12.z, fmaf(gb1, p11.z, fmaf(gb0, p10.z, p0.z)));
        va.w = fmaf(gb2, p12.w, fmaf(gb1, p11.w, fmaf(gb0, p10.w, p0.w)));
        vb.x = fmaf(gb2, q12.x, fmaf(gb1, q11.x, fmaf(gb0, q10.x, q0.x)));
        vb.y = fmaf(gb2, q12.y, fmaf(gb1, q11.y, fmaf(gb0, q10.y, q0.y)));
        vb.z = fmaf(gb2, q12.z, fmaf(gb1, q11.z, fmaf(gb0, q10.z, q0.z)));
        vb.w = fmaf(gb2, q12.w, fmaf(gb1, q11.w, fmaf(gb0, q10.w, q0.w)));
        oA[b * 8 + i4] = va;
        oB[b * 8 + i4] = vb;
    }
}

// ---------------------------------------------------------------------------
// kernel_launch — k_middle and k_expand launched with PDL
// (programmatic stream serialization) to hide launch gaps.
// ---------------------------------------------------------------------------
extern "C" void kernel_launch(void* const* d_in, const int* in_sizes, int n_in,
                              void* d_out, int out_size) {
    const float* feat = (const float*)d_in[0];
    const float* geo  = (const float*)d_in[1];
    const float* W1   = (const float*)d_in[2];
    const float* W2   = (const float*)d_in[3];
    const void*  nrm  = (n_in > 4) ? d_in[4] : nullptr;
    float* out = (float*)d_out;

    k_partial<<<BZ * NN / 2 + 9, 256>>>(feat, geo, W1, W2);

    cudaLaunchAttribute attr[1];
    attr[0].id = cudaLaunchAttributeProgrammaticStreamSerialization;
    attr[0].val.programmaticStreamSerializationAllowed = 1;

    {
        cudaLaunchConfig_t cfg = {};
        cfg.gridDim = dim3(BZ);
        cfg.blockDim = dim3(512);
        cfg.attrs = attr;
        cfg.numAttrs = 1;
        cudaLaunchKernelEx(&cfg, k_middle, geo);
    }
    {
        cudaLaunchConfig_t cfg = {};
        cfg.gridDim = dim3(BZ * NN / 2);
        cfg.blockDim = dim3(256);
        cfg.attrs = attr;
        cfg.numAttrs = 1;
        cudaLaunchKernelEx(&cfg, k_expand, geo, out, (const void*)nrm);
    }
}